// round 4
// baseline (speedup 1.0000x reference)
#include <cuda_runtime.h>

#define BN 2
#define CN 128
#define HN 96
#define WN 96
#define SP (HN*WN)            // 9216
#define TOT (BN*CN*SP)
#define EPSF 1e-8f

__device__ float g_scale[BN*SP];

typedef unsigned long long u64;

__device__ __forceinline__ u64 pk(float lo, float hi){
    u64 r; asm("mov.b64 %0,{%1,%2};" : "=l"(r) : "f"(lo), "f"(hi)); return r;
}
__device__ __forceinline__ void upk(u64 v, float& lo, float& hi){
    asm("mov.b64 {%0,%1},%2;" : "=f"(lo), "=f"(hi) : "l"(v));
}
__device__ __forceinline__ void ffma2(u64& d, u64 a, u64 b){
    asm("fma.rn.f32x2 %0,%1,%2,%0;" : "+l"(d) : "l"(a), "l"(b));
}
__device__ __forceinline__ u64 addf2(u64 a, u64 b){
    u64 r; asm("add.rn.f32x2 %0,%1,%2;" : "=l"(r) : "l"(a), "l"(b)); return r;
}

// ---------------------------------------------------------------------------
// block (4,4,K*CSPLIT): x=xg (8 px each -> 32 px row), y=row (4), z=(cg,dy).
// Each z-group handles window row dy for CH/CSPLIT channels of each chunk;
// partial dots reduced via smem. Staging is software-pipelined (LDG->regs for
// chunk k+1 while computing chunk k from double-buffered smem). Norms
// accumulate in registers during staging. FFMA2 packs r-pairs.
// ---------------------------------------------------------------------------
template<int K, int CSPLIT, bool SCALE_IN, bool EPI>
__global__ void __launch_bounds__(16*K*CSPLIT) sim_kernel(const float* __restrict__ src,
                                                          const float* __restrict__ thr_p,
                                                          float* __restrict__ outp)
{
    constexpr int H  = K/2, B0 = 4-H;
    constexpr int TX = 32, TY = 4;
    constexpr int SW = 40, SH = 12, NPIX = SW*SH;   // 480
    constexpr int CH = 16, NC = CN/CH, CHW = CH/CSPLIT;
    constexpr int NT = 16*K*CSPLIT;
    constexpr int NSLOT = K*16, RSTR = K*4+1;

    extern __shared__ float smem[];
    float* tile = smem;                       // 2*CH*NPIX (double buffer; red alias)
    float* nrm  = smem + 2*CH*NPIX;           // NPIX
    float* scl  = nrm + NPIX;                 // 128
    int*   scnt = (int*)(scl + 128);          // K*128
    u64*   red  = (u64*)tile;                 // valid after main loop

    const int xg = threadIdx.x;               // 0..3
    const int yy = threadIdx.y;               // 0..3
    const int z  = threadIdx.z;               // 0..K*CSPLIT-1
    const int cg = z / K;
    const int dy = z - cg*K;
    const int tid = xg + 4*yy + 16*z;

    const int gx0 = blockIdx.x*TX, gy0 = blockIdx.y*TY, b = blockIdx.z;
    const float thr = *thr_p;
    const float* __restrict__ srcb = src + (size_t)b*CN*SP;

    // ---- staging slots (<=2 pixels/thread), fully precomputed ----
    int pos[2]; const float* gp[2]; float sval[2]; bool okv[2]; float nsq[2];
    int npos = 0;
    #pragma unroll
    for (int j = 0; j < 2; j++) {
        int p = tid + j*NT;
        if (p < NPIX) {
            int sy = p/SW, sx = p - sy*SW;
            int gy = gy0+sy-4, gx = gx0+sx-4;
            bool ok = ((unsigned)gy<(unsigned)HN) && ((unsigned)gx<(unsigned)WN);
            if (H < 4)   // zero unused outer ring for K=5
                ok = ok && (sy>=B0) && (sy<8+H) && (sx>=B0) && (sx<36+H);
            int go = ok ? (gy*WN+gx) : 0;
            float sv = 1.f;
            if (SCALE_IN && ok) sv = g_scale[b*SP+go];
            pos[npos]=p; gp[npos]=srcb+go; sval[npos]=sv; okv[npos]=ok; nsq[npos]=0.f;
            npos++;
        }
    }

    float rs[2][CH];
    auto stage = [&](int c0){
        #pragma unroll
        for (int j = 0; j < 2; j++) if (j < npos) {
            const float* g = gp[j] + (size_t)c0*SP;
            #pragma unroll
            for (int c = 0; c < CH; c++) {
                float v = okv[j] ? g[c*SP] : 0.f;
                if (SCALE_IN) v *= sval[j];
                rs[j][c] = v;
            }
        }
    };
    auto dosts = [&](float* buf){
        #pragma unroll
        for (int j = 0; j < 2; j++) if (j < npos) {
            float* t = buf + pos[j];
            float s = 0.f;
            #pragma unroll
            for (int c = 0; c < CH; c++) { float v = rs[j][c]; s = fmaf(v,v,s); t[c*NPIX] = v; }
            nsq[j] += s;
        }
    };

    u64 acc2[K][4];
    #pragma unroll
    for (int dx = 0; dx < K; dx++)
        #pragma unroll
        for (int p = 0; p < 4; p++) acc2[dx][p] = 0ull;

    const int crow = (yy+4)*SW + xg*8 + 4;         // center, 16B aligned
    const int wrow = (yy+dy+B0)*SW + xg*8;         // window row, 16B aligned

    stage(0);
    dosts(tile);
    __syncthreads();

    #pragma unroll 1
    for (int k = 0; k < NC; k++) {
        if (k+1 < NC) stage((k+1)*CH);             // LDGs in flight over compute
        const float* tc0 = tile + (k&1)*CH*NPIX + cg*CHW*NPIX;
        #pragma unroll
        for (int c = 0; c < CHW; c++) {
            const float* tc = tc0 + c*NPIX;
            float4 a0 = *(const float4*)(tc+crow);
            float4 a1 = *(const float4*)(tc+crow+4);
            float4 w0 = *(const float4*)(tc+wrow);
            float4 w1 = *(const float4*)(tc+wrow+4);
            float4 w2 = *(const float4*)(tc+wrow+8);
            float4 w3 = *(const float4*)(tc+wrow+12);
            float w[16] = {w0.x,w0.y,w0.z,w0.w, w1.x,w1.y,w1.z,w1.w,
                           w2.x,w2.y,w2.z,w2.w, w3.x,w3.y,w3.z,w3.w};
            u64 cp[4] = {pk(a0.x,a0.y), pk(a0.z,a0.w), pk(a1.x,a1.y), pk(a1.z,a1.w)};
            u64 wp[15];
            #pragma unroll
            for (int j2 = 0; j2 < 15; j2++) wp[j2] = pk(w[j2], w[j2+1]);
            #pragma unroll
            for (int dx = 0; dx < K; dx++)
                #pragma unroll
                for (int p = 0; p < 4; p++)
                    ffma2(acc2[dx][p], cp[p], wp[B0+dx+2*p]);
        }
        if (k+1 < NC) dosts(tile + ((k+1)&1)*CH*NPIX);
        __syncthreads();
    }

    // norms (register-accumulated) -> smem
    #pragma unroll
    for (int j = 0; j < 2; j++) if (j < npos) nrm[pos[j]] = sqrtf(nsq[j]);

    // channel-group reduction (tile no longer read; alias as red)
    const int slot = (dy*4+yy)*4 + xg;
    if (cg > 0) {
        u64* r0 = red + ((cg-1)*NSLOT + slot)*RSTR;
        #pragma unroll
        for (int dx = 0; dx < K; dx++)
            #pragma unroll
            for (int p = 0; p < 4; p++) r0[dx*4+p] = acc2[dx][p];
    }
    __syncthreads();

    if (cg == 0) {
        #pragma unroll
        for (int wsrc = 1; wsrc < CSPLIT; wsrc++) {
            const u64* r0 = red + ((wsrc-1)*NSLOT + slot)*RSTR;
            #pragma unroll
            for (int dx = 0; dx < K; dx++)
                #pragma unroll
                for (int p = 0; p < 4; p++) acc2[dx][p] = addf2(acc2[dx][p], r0[dx*4+p]);
        }
        // threshold
        float4 n0 = *(const float4*)(nrm+crow);
        float4 n1 = *(const float4*)(nrm+crow+4);
        float4 m0 = *(const float4*)(nrm+wrow);
        float4 m1 = *(const float4*)(nrm+wrow+4);
        float4 m2 = *(const float4*)(nrm+wrow+8);
        float4 m3 = *(const float4*)(nrm+wrow+12);
        float ncn[8] = {n0.x,n0.y,n0.z,n0.w, n1.x,n1.y,n1.z,n1.w};
        float nw[16] = {m0.x,m0.y,m0.z,m0.w, m1.x,m1.y,m1.z,m1.w,
                        m2.x,m2.y,m2.z,m2.w, m3.x,m3.y,m3.z,m3.w};
        int cnt[8] = {0,0,0,0,0,0,0,0};
        #pragma unroll
        for (int dx = 0; dx < K; dx++) {
            bool ctr = (dy == H) && (dx == H);
            #pragma unroll
            for (int p = 0; p < 4; p++) {
                float lo, hi; upk(acc2[dx][p], lo, hi);
                int r = 2*p;
                float mlo = fmaxf(ncn[r]  *nw[B0+dx+r],   EPSF);
                float mhi = fmaxf(ncn[r+1]*nw[B0+dx+r+1], EPSF);
                if (!ctr) {
                    cnt[r]   += (lo < thr*mlo) ? 1 : 0;
                    cnt[r+1] += (hi < thr*mhi) ? 1 : 0;
                }
            }
        }
        #pragma unroll
        for (int r = 0; r < 8; r++)
            scnt[dy*128 + yy*32 + xg*8 + r] = cnt[r];
    }
    __syncthreads();

    if (tid < 128) {
        int s = 0;
        #pragma unroll
        for (int d = 0; d < K; d++) s += scnt[d*128 + tid];
        float sc = 1.f + sqrtf((float)s);
        if (EPI) scl[tid] = sc;
        else {
            int py = tid >> 5, px = tid & 31;
            g_scale[b*SP + (gy0+py)*WN + gx0+px] = sc;
        }
    }

    if (EPI) {
        __syncthreads();
        float* __restrict__ ob = outp + (size_t)b*CN*SP;
        #pragma unroll 1
        for (int i = tid; i < CN*32; i += NT) {   // 32 float4s per 128-px tile
            int c = i >> 5, q = i & 31;
            int py = q >> 3, qx = q & 7;
            int off = c*SP + (gy0+py)*WN + gx0 + qx*4;
            float4 v  = *(const float4*)(srcb + off);
            float4 s4 = *(const float4*)(scl + py*32 + qx*4);
            v.x *= s4.x; v.y *= s4.y; v.z *= s4.z; v.w *= s4.w;
            *(float4*)(ob + off) = v;
        }
    }
}

extern "C" void kernel_launch(void* const* d_in, const int* in_sizes, int n_in,
                              void* d_out, int out_size)
{
    const float* x  = (const float*)d_in[0];
    const float* t1 = (const float*)d_in[1];
    const float* t2 = (const float*)d_in[2];
    float* out = (float*)d_out;

    constexpr int SBASE = (2*16*480 + 480 + 128)*4;
    constexpr int SMEM9 = SBASE + 9*128*4;   // 68480 B
    constexpr int SMEM5 = SBASE + 5*128*4;   // 66432 B
    cudaFuncSetAttribute((const void*)sim_kernel<9,2,false,false>,
                         cudaFuncAttributeMaxDynamicSharedMemorySize, SMEM9);
    cudaFuncSetAttribute((const void*)sim_kernel<5,4,true,true>,
                         cudaFuncAttributeMaxDynamicSharedMemorySize, SMEM5);

    dim3 grid(WN/32, HN/4, BN);   // 144 blocks

    // Stage 1: 9x9 similarity on x -> g_scale       (block 288 thr, 9 warps)
    sim_kernel<9,2,false,false><<<grid, dim3(4,4,18), SMEM9>>>(x, t1, nullptr);
    // Stage 2: 5x5 on (x*scale1), fused final apply (block 320 thr, 10 warps)
    sim_kernel<5,4,true,true><<<grid, dim3(4,4,20), SMEM5>>>(x, t2, out);
}